// round 1
// baseline (speedup 1.0000x reference)
#include <cuda_runtime.h>

#define N_PTS 8192
#define DTOK  256
#define KNN_K 16
#define D_IN  259          // DTOK + 3
#define NW    512          // concatenated output cols of gemm1: [A | B]

// ---------------- scratch (device globals; no allocation allowed) ----------
__device__ float g_X[N_PTS * D_IN];        // layer input  (feat|xyz) then (out1|xyz)
__device__ float g_AB[N_PTS * NW];         // A (cols 0..255, includes b1) | B (cols 256..511)
__device__ float g_Wcat_a[D_IN * NW];      // [W1top - W1bot | W1bot] layer a
__device__ float g_Wcat_b[D_IN * NW];      // same, layer b
__device__ int   g_nbr[N_PTS * KNN_K];

// ---------------- weight prep ----------------------------------------------
__global__ void prep_weights(const float* __restrict__ W1a,
                             const float* __restrict__ W1b) {
    int idx = blockIdx.x * blockDim.x + threadIdx.x;
    if (idx >= D_IN * NW) return;
    int r = idx / NW, c = idx % NW;
    if (c < DTOK) {
        g_Wcat_a[idx] = W1a[r * DTOK + c] - W1a[(D_IN + r) * DTOK + c];
        g_Wcat_b[idx] = W1b[r * DTOK + c] - W1b[(D_IN + r) * DTOK + c];
    } else {
        int cc = c - DTOK;
        g_Wcat_a[idx] = W1a[(D_IN + r) * DTOK + cc];
        g_Wcat_b[idx] = W1b[(D_IN + r) * DTOK + cc];
    }
}

// ---------------- build X1 = [feat | xyz] -----------------------------------
__global__ void build_x(const float* __restrict__ feat,
                        const float* __restrict__ xyz) {
    int idx = blockIdx.x * blockDim.x + threadIdx.x;
    if (idx >= N_PTS * D_IN) return;
    int i = idx / D_IN, c = idx % D_IN;
    g_X[idx] = (c < DTOK) ? feat[i * DTOK + c] : xyz[i * 3 + (c - DTOK)];
}

// ---------------- KNN: per-thread top-16 insertion sort ---------------------
#define KNN_TPB  128
#define KNN_TILE 512
__global__ __launch_bounds__(KNN_TPB)
void knn_kernel(const float* __restrict__ xyz) {
    __shared__ float sx[KNN_TILE * 3];
    __shared__ float ssq[KNN_TILE];
    __shared__ float sd[KNN_K * KNN_TPB];
    __shared__ int   si[KNN_K * KNN_TPB];

    int tid = threadIdx.x;
    int i = blockIdx.x * KNN_TPB + tid;
    float xi0 = xyz[i * 3 + 0];
    float xi1 = xyz[i * 3 + 1];
    float xi2 = xyz[i * 3 + 2];
    float sqi = xi0 * xi0 + xi1 * xi1 + xi2 * xi2;

    #pragma unroll
    for (int s = 0; s < KNN_K; s++) sd[s * KNN_TPB + tid] = 1e30f;
    float worst = 1e30f;

    for (int j0 = 0; j0 < N_PTS; j0 += KNN_TILE) {
        __syncthreads();
        for (int t = tid; t < KNN_TILE; t += KNN_TPB) {
            float a = xyz[(j0 + t) * 3 + 0];
            float b = xyz[(j0 + t) * 3 + 1];
            float c = xyz[(j0 + t) * 3 + 2];
            sx[t * 3 + 0] = a; sx[t * 3 + 1] = b; sx[t * 3 + 2] = c;
            ssq[t] = a * a + b * b + c * c;
        }
        __syncthreads();
        for (int jj = 0; jj < KNN_TILE; jj++) {
            float dot = xi0 * sx[jj * 3] + xi1 * sx[jj * 3 + 1] + xi2 * sx[jj * 3 + 2];
            float dist = sqi - 2.0f * dot + ssq[jj];
            int j = j0 + jj;
            if (dist < worst && j != i) {
                int p = KNN_K - 1;
                while (p > 0 && sd[(p - 1) * KNN_TPB + tid] > dist) {
                    sd[p * KNN_TPB + tid] = sd[(p - 1) * KNN_TPB + tid];
                    si[p * KNN_TPB + tid] = si[(p - 1) * KNN_TPB + tid];
                    p--;
                }
                sd[p * KNN_TPB + tid] = dist;
                si[p * KNN_TPB + tid] = j;
                worst = sd[(KNN_K - 1) * KNN_TPB + tid];
            }
        }
    }
    #pragma unroll
    for (int s = 0; s < KNN_K; s++)
        g_nbr[i * KNN_K + s] = si[s * KNN_TPB + tid];
}

// ---------------- GEMM1: C[M,Nc] = X[M,Kd] @ W[Kd,Nc] (+bias on cols<bias_cols)
#define BM 64
#define BN 64
#define BK 16
__global__ __launch_bounds__(256)
void gemm_bias(const float* __restrict__ Xp, const float* __restrict__ Wp,
               const float* __restrict__ bias, float* __restrict__ C,
               int M, int Nc, int Kd, int bias_cols) {
    __shared__ float Xs[BK][BM];
    __shared__ float Ws[BK][BN];
    int tid = threadIdx.x;
    int tx = tid % 16, ty = tid / 16;
    int bm = blockIdx.y * BM, bn = blockIdx.x * BN;
    float acc[4][4] = {};

    for (int k0 = 0; k0 < Kd; k0 += BK) {
        for (int l = tid; l < BM * BK; l += 256) {
            int m = l / BK, kk = l % BK;
            float v = 0.f;
            if (k0 + kk < Kd) v = Xp[(bm + m) * Kd + k0 + kk];
            Xs[kk][m] = v;
        }
        for (int l = tid; l < BN * BK; l += 256) {
            int kk = l / BN, n = l % BN;
            float v = 0.f;
            if (k0 + kk < Kd) v = Wp[(k0 + kk) * Nc + bn + n];
            Ws[kk][n] = v;
        }
        __syncthreads();
        #pragma unroll
        for (int kk = 0; kk < BK; kk++) {
            float a[4], b[4];
            #pragma unroll
            for (int u = 0; u < 4; u++) a[u] = Xs[kk][ty * 4 + u];
            #pragma unroll
            for (int u = 0; u < 4; u++) b[u] = Ws[kk][tx * 4 + u];
            #pragma unroll
            for (int u = 0; u < 4; u++)
                #pragma unroll
                for (int v = 0; v < 4; v++)
                    acc[u][v] = fmaf(a[u], b[v], acc[u][v]);
        }
        __syncthreads();
    }
    #pragma unroll
    for (int u = 0; u < 4; u++) {
        int m = bm + ty * 4 + u;
        #pragma unroll
        for (int v = 0; v < 4; v++) {
            int n = bn + tx * 4 + v;
            float val = acc[u][v];
            if (n < bias_cols) val += bias[n];
            C[m * Nc + n] = val;
        }
    }
}

// ---------------- edge kernel: out_i = max_k relu(A_i + B_jk) @ W2 + b2 -----
__global__ __launch_bounds__(256)
void edge_kernel(const float* __restrict__ AB, const float* __restrict__ W2,
                 const float* __restrict__ b2, float* __restrict__ out,
                 int ostride) {
    __shared__ float Hs[DTOK * KNN_K];   // [d][k] layout, 16 KB
    __shared__ int snbr[KNN_K];

    int i = blockIdx.x;
    int t = threadIdx.x;                 // 256 threads = 256 d / output cols
    if (t < KNN_K) snbr[t] = g_nbr[i * KNN_K + t];
    __syncthreads();

    float a = AB[i * NW + t];            // A_i[t] (includes b1)
    float h[KNN_K];
    #pragma unroll
    for (int k = 0; k < KNN_K; k++) {
        float b = AB[snbr[k] * NW + DTOK + t];   // B_jk[t]
        h[k] = fmaxf(a + b, 0.f);
    }
    #pragma unroll
    for (int k4 = 0; k4 < KNN_K; k4 += 4) {
        *(float4*)&Hs[t * KNN_K + k4] = make_float4(h[k4], h[k4 + 1], h[k4 + 2], h[k4 + 3]);
    }
    __syncthreads();

    float acc[KNN_K];
    #pragma unroll
    for (int k = 0; k < KNN_K; k++) acc[k] = 0.f;

    #pragma unroll 4
    for (int d = 0; d < DTOK; d++) {
        float w = W2[d * DTOK + t];                       // coalesced, L2-hot
        float4 h0 = *(const float4*)&Hs[d * KNN_K + 0];   // broadcast LDS
        float4 h1 = *(const float4*)&Hs[d * KNN_K + 4];
        float4 h2 = *(const float4*)&Hs[d * KNN_K + 8];
        float4 h3 = *(const float4*)&Hs[d * KNN_K + 12];
        acc[0]  = fmaf(h0.x, w, acc[0]);
        acc[1]  = fmaf(h0.y, w, acc[1]);
        acc[2]  = fmaf(h0.z, w, acc[2]);
        acc[3]  = fmaf(h0.w, w, acc[3]);
        acc[4]  = fmaf(h1.x, w, acc[4]);
        acc[5]  = fmaf(h1.y, w, acc[5]);
        acc[6]  = fmaf(h1.z, w, acc[6]);
        acc[7]  = fmaf(h1.w, w, acc[7]);
        acc[8]  = fmaf(h2.x, w, acc[8]);
        acc[9]  = fmaf(h2.y, w, acc[9]);
        acc[10] = fmaf(h2.z, w, acc[10]);
        acc[11] = fmaf(h2.w, w, acc[11]);
        acc[12] = fmaf(h3.x, w, acc[12]);
        acc[13] = fmaf(h3.y, w, acc[13]);
        acc[14] = fmaf(h3.z, w, acc[14]);
        acc[15] = fmaf(h3.w, w, acc[15]);
    }

    float m = acc[0];
    #pragma unroll
    for (int k = 1; k < KNN_K; k++) m = fmaxf(m, acc[k]);
    out[i * ostride + t] = m + b2[t];
}

// ---------------- launch ----------------------------------------------------
extern "C" void kernel_launch(void* const* d_in, const int* in_sizes, int n_in,
                              void* d_out, int out_size) {
    const float* xyz  = (const float*)d_in[0];
    const float* feat = (const float*)d_in[1];
    const float* W1a  = (const float*)d_in[2];
    const float* b1a  = (const float*)d_in[3];
    const float* W2a  = (const float*)d_in[4];
    const float* b2a  = (const float*)d_in[5];
    const float* W1b  = (const float*)d_in[6];
    const float* b1b  = (const float*)d_in[7];
    const float* W2b  = (const float*)d_in[8];
    const float* b2b  = (const float*)d_in[9];
    float* out = (float*)d_out;

    float *gX, *gAB, *gWa, *gWb;
    cudaGetSymbolAddress((void**)&gX,  g_X);
    cudaGetSymbolAddress((void**)&gAB, g_AB);
    cudaGetSymbolAddress((void**)&gWa, g_Wcat_a);
    cudaGetSymbolAddress((void**)&gWb, g_Wcat_b);

    // 1) weight prep
    {
        int n = D_IN * NW;
        prep_weights<<<(n + 255) / 256, 256>>>(W1a, W1b);
    }
    // 2) KNN
    knn_kernel<<<N_PTS / KNN_TPB, KNN_TPB>>>(xyz);
    // 3) X1 = [feat | xyz]
    {
        int n = N_PTS * D_IN;
        build_x<<<(n + 255) / 256, 256>>>(feat, xyz);
    }
    dim3 ggrid(NW / BN, N_PTS / BM);

    // layer a
    gemm_bias<<<ggrid, 256>>>(gX, gWa, b1a, gAB, N_PTS, NW, D_IN, DTOK);
    edge_kernel<<<N_PTS, 256>>>(gAB, W2a, b2a, gX, D_IN);   // writes cols 0..255 of X; xyz cols persist

    // layer b
    gemm_bias<<<ggrid, 256>>>(gX, gWb, b1b, gAB, N_PTS, NW, D_IN, DTOK);
    edge_kernel<<<N_PTS, 256>>>(gAB, W2b, b2b, out, DTOK);
}

// round 3
// speedup vs baseline: 1.5277x; 1.5277x over previous
#include <cuda_runtime.h>

#define N_PTS 8192
#define DTOK  256
#define KNN_K 16
#define D_IN  259          // DTOK + 3
#define NW    512          // concatenated output cols of gemm1: [A | B]

typedef unsigned long long u64;

// ---------------- f32x2 packed helpers (sm_100+) ----------------------------
__device__ __forceinline__ u64 pack2(float lo, float hi) {
    u64 r;
    asm("mov.b64 %0, {%1, %2};" : "=l"(r) : "f"(lo), "f"(hi));
    return r;
}
__device__ __forceinline__ u64 fma2(u64 a, u64 b, u64 c) {
    u64 d;
    asm("fma.rn.f32x2 %0, %1, %2, %3;" : "=l"(d) : "l"(a), "l"(b), "l"(c));
    return d;
}
__device__ __forceinline__ float2 unpack2(u64 v) {
    float2 f;
    asm("mov.b64 {%0, %1}, %2;" : "=f"(f.x), "=f"(f.y) : "l"(v));
    return f;
}

// ---------------- scratch (device globals; no allocation allowed) ----------
__device__ float g_X[N_PTS * D_IN];        // layer input  (feat|xyz) then (out1|xyz)
__device__ float g_AB[N_PTS * NW];         // A (cols 0..255, includes b1) | B (cols 256..511)
__device__ float g_Wcat_a[D_IN * NW];      // [W1top - W1bot | W1bot] layer a
__device__ float g_Wcat_b[D_IN * NW];      // same, layer b
__device__ int   g_nbr[N_PTS * KNN_K];

// ---------------- weight prep ----------------------------------------------
__global__ void prep_weights(const float* __restrict__ W1a,
                             const float* __restrict__ W1b) {
    int idx = blockIdx.x * blockDim.x + threadIdx.x;
    if (idx >= D_IN * NW) return;
    int r = idx / NW, c = idx % NW;
    if (c < DTOK) {
        g_Wcat_a[idx] = W1a[r * DTOK + c] - W1a[(D_IN + r) * DTOK + c];
        g_Wcat_b[idx] = W1b[r * DTOK + c] - W1b[(D_IN + r) * DTOK + c];
    } else {
        int cc = c - DTOK;
        g_Wcat_a[idx] = W1a[(D_IN + r) * DTOK + cc];
        g_Wcat_b[idx] = W1b[(D_IN + r) * DTOK + cc];
    }
}

// ---------------- build X1 = [feat | xyz] -----------------------------------
__global__ void build_x(const float* __restrict__ feat,
                        const float* __restrict__ xyz) {
    int idx = blockIdx.x * blockDim.x + threadIdx.x;
    if (idx >= N_PTS * D_IN) return;
    int i = idx / D_IN, c = idx % D_IN;
    g_X[idx] = (c < DTOK) ? feat[i * DTOK + c] : xyz[i * 3 + (c - DTOK)];
}

// ---------------- KNN: one warp per query, register top-16 ------------------
#define KNN_WPB   8        // warps (= queries) per block
#define KNN_TILE  2048     // candidates per shared tile

struct DI { float d; int i; };

__global__ __launch_bounds__(256)
void knn_kernel(const float* __restrict__ xyz) {
    // 32KB buffer: scan phase = float4 (x,y,z,sq) tile; merge phase = DI pairs
    __shared__ __align__(16) float4 buf[KNN_TILE];

    int warp = threadIdx.x >> 5, lane = threadIdx.x & 31;
    int q = blockIdx.x * KNN_WPB + warp;

    float xi0 = xyz[q * 3 + 0];
    float xi1 = xyz[q * 3 + 1];
    float xi2 = xyz[q * 3 + 2];
    float sqi = fmaf(xi0, xi0, fmaf(xi1, xi1, xi2 * xi2));

    float d16[KNN_K];
    int   i16[KNN_K];
    #pragma unroll
    for (int s = 0; s < KNN_K; s++) { d16[s] = 1e30f; i16[s] = -1; }

    for (int t0 = 0; t0 < N_PTS; t0 += KNN_TILE) {
        __syncthreads();
        // cooperative tile load: 256 threads x 8 points
        for (int t = threadIdx.x; t < KNN_TILE; t += 256) {
            int j = t0 + t;
            float a = xyz[j * 3 + 0];
            float b = xyz[j * 3 + 1];
            float c = xyz[j * 3 + 2];
            buf[t] = make_float4(a, b, c, fmaf(a, a, fmaf(b, b, c * c)));
        }
        __syncthreads();

        #pragma unroll 4
        for (int jj = lane; jj < KNN_TILE; jj += 32) {
            float4 p = buf[jj];
            float dot = fmaf(xi0, p.x, fmaf(xi1, p.y, xi2 * p.z));
            float dist = (sqi + p.w) - 2.0f * dot;
            int j = t0 + jj;
            if (j == q) dist = 1e30f;
            if (dist < d16[KNN_K - 1]) {
                float dk = dist; int ik = j;
                #pragma unroll
                for (int s = 0; s < KNN_K; s++) {
                    if (dk < d16[s]) {
                        float tf = d16[s]; d16[s] = dk; dk = tf;
                        int   ti = i16[s]; i16[s] = ik; ik = ti;
                    }
                }
            }
        }
    }
    __syncthreads();   // tile buffer free; reuse for merge

    // dump sorted per-lane lists: layout [warp][s][lane] (2-way conflicts max)
    DI* pairs = (DI*)buf;
    DI* wp = pairs + warp * (KNN_K * 32);
    #pragma unroll
    for (int s = 0; s < KNN_K; s++) {
        DI e; e.d = d16[s]; e.i = i16[s];
        wp[s * 32 + lane] = e;
    }
    __syncwarp();

    // merge 32 sorted lists: 16 rounds of warp-argmin over current heads
    int ptr = 0;
    #pragma unroll 1
    for (int r = 0; r < KNN_K; r++) {
        DI h = wp[ptr * 32 + lane];
        float bd = h.d; int bi = h.i;
        #pragma unroll
        for (int off = 16; off > 0; off >>= 1) {
            float od = __shfl_xor_sync(0xFFFFFFFFu, bd, off);
            int   oi = __shfl_xor_sync(0xFFFFFFFFu, bi, off);
            if (od < bd || (od == bd && oi < bi)) { bd = od; bi = oi; }
        }
        if (h.d == bd && h.i == bi) ptr++;      // unique winner (indices disjoint)
        if (lane == 0) g_nbr[q * KNN_K + r] = bi;
    }
}

// ---------------- GEMM1: C[M,Nc] = X[M,Kd] @ W[Kd,Nc] (+bias on cols<bias_cols)
#define BM 64
#define BN 64
#define BK 16
__global__ __launch_bounds__(256)
void gemm_bias(const float* __restrict__ Xp, const float* __restrict__ Wp,
               const float* __restrict__ bias, float* __restrict__ C,
               int M, int Nc, int Kd, int bias_cols) {
    __shared__ __align__(16) float Xs[BK][BM];
    __shared__ __align__(16) float Ws[BK][BN];
    int tid = threadIdx.x;
    int tx = tid % 16, ty = tid / 16;
    int bm = blockIdx.y * BM, bn = blockIdx.x * BN;

    u64 acc[4][2];
    #pragma unroll
    for (int u = 0; u < 4; u++) { acc[u][0] = 0ull; acc[u][1] = 0ull; }

    for (int k0 = 0; k0 < Kd; k0 += BK) {
        for (int l = tid; l < BM * BK; l += 256) {
            int m = l / BK, kk = l % BK;
            float v = 0.f;
            if (k0 + kk < Kd) v = Xp[(bm + m) * Kd + k0 + kk];
            Xs[kk][m] = v;
        }
        for (int l = tid; l < BN * BK; l += 256) {
            int kk = l / BN, n = l % BN;
            float v = 0.f;
            if (k0 + kk < Kd) v = Wp[(k0 + kk) * Nc + bn + n];
            Ws[kk][n] = v;
        }
        __syncthreads();
        #pragma unroll
        for (int kk = 0; kk < BK; kk++) {
            float4 av = *(const float4*)&Xs[kk][ty * 4];
            ulonglong2 bq = *(const ulonglong2*)&Ws[kk][tx * 4];
            u64 a0 = pack2(av.x, av.x);
            u64 a1 = pack2(av.y, av.y);
            u64 a2 = pack2(av.z, av.z);
            u64 a3 = pack2(av.w, av.w);
            acc[0][0] = fma2(a0, bq.x, acc[0][0]);
            acc[0][1] = fma2(a0, bq.y, acc[0][1]);
            acc[1][0] = fma2(a1, bq.x, acc[1][0]);
            acc[1][1] = fma2(a1, bq.y, acc[1][1]);
            acc[2][0] = fma2(a2, bq.x, acc[2][0]);
            acc[2][1] = fma2(a2, bq.y, acc[2][1]);
            acc[3][0] = fma2(a3, bq.x, acc[3][0]);
            acc[3][1] = fma2(a3, bq.y, acc[3][1]);
        }
        __syncthreads();
    }
    #pragma unroll
    for (int u = 0; u < 4; u++) {
        int m = bm + ty * 4 + u;
        float2 v01 = unpack2(acc[u][0]);
        float2 v23 = unpack2(acc[u][1]);
        float vals[4] = {v01.x, v01.y, v23.x, v23.y};
        #pragma unroll
        for (int v = 0; v < 4; v++) {
            int n = bn + tx * 4 + v;
            float val = vals[v];
            if (n < bias_cols) val += bias[n];
            C[m * Nc + n] = val;
        }
    }
}

// ---------------- edge kernel: out_i = max_k relu(A_i + B_jk) @ W2 + b2 -----
__global__ __launch_bounds__(256)
void edge_kernel(const float* __restrict__ AB, const float* __restrict__ W2,
                 const float* __restrict__ b2, float* __restrict__ out,
                 int ostride) {
    __shared__ __align__(16) float Hs[DTOK * KNN_K];   // [d][k] layout, 16 KB
    __shared__ int snbr[KNN_K];

    int i = blockIdx.x;
    int t = threadIdx.x;                 // 256 threads = 256 d / output cols
    if (t < KNN_K) snbr[t] = g_nbr[i * KNN_K + t];
    __syncthreads();

    float a = AB[i * NW + t];            // A_i[t] (includes b1)
    float h[KNN_K];
    #pragma unroll
    for (int k = 0; k < KNN_K; k++) {
        float b = AB[snbr[k] * NW + DTOK + t];   // B_jk[t]
        h[k] = fmaxf(a + b, 0.f);
    }
    #pragma unroll
    for (int k4 = 0; k4 < KNN_K; k4 += 4) {
        *(float4*)&Hs[t * KNN_K + k4] = make_float4(h[k4], h[k4 + 1], h[k4 + 2], h[k4 + 3]);
    }
    __syncthreads();

    u64 acc[8];
    #pragma unroll
    for (int p = 0; p < 8; p++) acc[p] = 0ull;

    #pragma unroll 4
    for (int d = 0; d < DTOK; d++) {
        float w = W2[d * DTOK + t];                       // coalesced, L2-hot
        u64 ww = pack2(w, w);
        const ulonglong2* hp = (const ulonglong2*)&Hs[d * KNN_K];
        ulonglong2 q0 = hp[0];
        ulonglong2 q1 = hp[1];
        ulonglong2 q2 = hp[2];
        ulonglong2 q3 = hp[3];
        acc[0] = fma2(q0.x, ww, acc[0]);
        acc[1] = fma2(q0.y, ww, acc[1]);
        acc[2] = fma2(q1.x, ww, acc[2]);
        acc[3] = fma2(q1.y, ww, acc[3]);
        acc[4] = fma2(q2.x, ww, acc[4]);
        acc[5] = fma2(q2.y, ww, acc[5]);
        acc[6] = fma2(q3.x, ww, acc[6]);
        acc[7] = fma2(q3.y, ww, acc[7]);
    }

    float m = -1e30f;
    #pragma unroll
    for (int p = 0; p < 8; p++) {
        float2 f = unpack2(acc[p]);
        m = fmaxf(m, fmaxf(f.x, f.y));
    }
    out[i * ostride + t] = m + b2[t];
}

// ---------------- launch ----------------------------------------------------
extern "C" void kernel_launch(void* const* d_in, const int* in_sizes, int n_in,
                              void* d_out, int out_size) {
    const float* xyz  = (const float*)d_in[0];
    const float* feat = (const float*)d_in[1];
    const float* W1a  = (const float*)d_in[2];
    const float* b1a  = (const float*)d_in[3];
    const float* W2a  = (const float*)d_in[4];
    const float* b2a  = (const float*)d_in[5];
    const float* W1b  = (const float*)d_in[6];
    const float* b1b  = (const float*)d_in[7];
    const float* W2b  = (const float*)d_in[8];
    const float* b2b  = (const float*)d_in[9];
    float* out = (float*)d_out;

    float *gX, *gAB, *gWa, *gWb;
    cudaGetSymbolAddress((void**)&gX,  g_X);
    cudaGetSymbolAddress((void**)&gAB, g_AB);
    cudaGetSymbolAddress((void**)&gWa, g_Wcat_a);
    cudaGetSymbolAddress((void**)&gWb, g_Wcat_b);

    // 1) weight prep
    {
        int n = D_IN * NW;
        prep_weights<<<(n + 255) / 256, 256>>>(W1a, W1b);
    }
    // 2) KNN (warp per query)
    knn_kernel<<<N_PTS / KNN_WPB, 256>>>(xyz);
    // 3) X1 = [feat | xyz]
    {
        int n = N_PTS * D_IN;
        build_x<<<(n + 255) / 256, 256>>>(feat, xyz);
    }
    dim3 ggrid(NW / BN, N_PTS / BM);

    // layer a
    gemm_bias<<<ggrid, 256>>>(gX, gWa, b1a, gAB, N_PTS, NW, D_IN, DTOK);
    edge_kernel<<<N_PTS, 256>>>(gAB, W2a, b2a, gX, D_IN);   // writes cols 0..255 of X; xyz cols persist

    // layer b
    gemm_bias<<<ggrid, 256>>>(gX, gWb, b1b, gAB, N_PTS, NW, D_IN, DTOK);
    edge_kernel<<<N_PTS, 256>>>(gAB, W2b, b2b, out, DTOK);
}

// round 9
// speedup vs baseline: 2.8170x; 1.8440x over previous
#include <cuda_runtime.h>
#include <cuda_fp16.h>
#include <cstdint>

#define N_PTS 8192
#define DTOK  256
#define KNN_K 16
#define D_IN  259          // DTOK + 3
#define NW    512          // concatenated output cols of gemm1: [A | B]

typedef unsigned long long u64;

// ---------------- f32x2 packed helpers (sm_100+) ----------------------------
__device__ __forceinline__ u64 pack2(float lo, float hi) {
    u64 r;
    asm("mov.b64 %0, {%1, %2};" : "=l"(r) : "f"(lo), "f"(hi));
    return r;
}
__device__ __forceinline__ u64 fma2(u64 a, u64 b, u64 c) {
    u64 d;
    asm("fma.rn.f32x2 %0, %1, %2, %3;" : "=l"(d) : "l"(a), "l"(b), "l"(c));
    return d;
}
__device__ __forceinline__ float2 unpack2(u64 v) {
    float2 f;
    asm("mov.b64 {%0, %1}, %2;" : "=f"(f.x), "=f"(f.y) : "l"(v));
    return f;
}

// ---------------- warp MMA helpers (family-level PTX) ------------------------
__device__ __forceinline__ uint32_t smem_u32(const void* p) {
    uint32_t a;
    asm("{ .reg .u64 t; cvta.to.shared.u64 t, %1; cvt.u32.u64 %0, t; }" : "=r"(a) : "l"(p));
    return a;
}
__device__ __forceinline__ void ldsm_x4(uint32_t& r0, uint32_t& r1, uint32_t& r2,
                                        uint32_t& r3, uint32_t addr) {
    asm volatile("ldmatrix.sync.aligned.m8n8.x4.shared.b16 {%0,%1,%2,%3}, [%4];"
                 : "=r"(r0), "=r"(r1), "=r"(r2), "=r"(r3) : "r"(addr));
}
__device__ __forceinline__ void mma_f16(float* c, uint32_t a0, uint32_t a1,
                                        uint32_t a2, uint32_t a3,
                                        uint32_t b0, uint32_t b1) {
    asm volatile(
        "mma.sync.aligned.m16n8k16.row.col.f32.f16.f16.f32 "
        "{%0,%1,%2,%3}, {%4,%5,%6,%7}, {%8,%9}, {%0,%1,%2,%3};"
        : "+f"(c[0]), "+f"(c[1]), "+f"(c[2]), "+f"(c[3])
        : "r"(a0), "r"(a1), "r"(a2), "r"(a3), "r"(b0), "r"(b1));
}

// ---------------- scratch (device globals; no allocation allowed) ----------
__device__ float g_X[N_PTS * D_IN];
__device__ float g_AB[N_PTS * NW];
__device__ float g_Wcat_a[D_IN * NW];
__device__ float g_Wcat_b[D_IN * NW];
__device__ int   g_nbr[N_PTS * KNN_K];
__device__ __align__(16) __half g_W2t_a[DTOK * DTOK];
__device__ __align__(16) __half g_W2t_b[DTOK * DTOK];

// ---------------- weight prep ----------------------------------------------
__global__ void prep_weights(const float* __restrict__ W1a,
                             const float* __restrict__ W1b,
                             const float* __restrict__ W2a,
                             const float* __restrict__ W2b) {
    int idx = blockIdx.x * blockDim.x + threadIdx.x;
    if (idx < D_IN * NW) {
        int r = idx / NW, c = idx % NW;
        if (c < DTOK) {
            g_Wcat_a[idx] = W1a[r * DTOK + c] - W1a[(D_IN + r) * DTOK + c];
            g_Wcat_b[idx] = W1b[r * DTOK + c] - W1b[(D_IN + r) * DTOK + c];
        } else {
            int cc = c - DTOK;
            g_Wcat_a[idx] = W1a[(D_IN + r) * DTOK + cc];
            g_Wcat_b[idx] = W1b[(D_IN + r) * DTOK + cc];
        }
    }
    if (idx < DTOK * DTOK) {
        int n = idx / DTOK, d = idx % DTOK;
        g_W2t_a[idx] = __float2half_rn(W2a[d * DTOK + n]);
        g_W2t_b[idx] = __float2half_rn(W2b[d * DTOK + n]);
    }
}

// ---------------- build X1 = [feat | xyz] -----------------------------------
__global__ void build_x(const float* __restrict__ feat,
                        const float* __restrict__ xyz) {
    int idx = blockIdx.x * blockDim.x + threadIdx.x;
    if (idx >= N_PTS * D_IN) return;
    int i = idx / D_IN, c = idx % D_IN;
    g_X[idx] = (c < DTOK) ? feat[i * DTOK + c] : xyz[i * 3 + (c - DTOK)];
}

// ---------------- KNN: one warp per query, register top-16 ------------------
#define KNN_WPB   8
#define KNN_TILE  2048
struct DI { float d; int i; };

__global__ __launch_bounds__(256)
void knn_kernel(const float* __restrict__ xyz) {
    __shared__ __align__(16) float4 buf[KNN_TILE];
    int warp = threadIdx.x >> 5, lane = threadIdx.x & 31;
    int q = blockIdx.x * KNN_WPB + warp;

    float xi0 = xyz[q * 3 + 0];
    float xi1 = xyz[q * 3 + 1];
    float xi2 = xyz[q * 3 + 2];
    float sqi = fmaf(xi0, xi0, fmaf(xi1, xi1, xi2 * xi2));

    float d16[KNN_K];
    int   i16[KNN_K];
    #pragma unroll
    for (int s = 0; s < KNN_K; s++) { d16[s] = 1e30f; i16[s] = -1; }

    for (int t0 = 0; t0 < N_PTS; t0 += KNN_TILE) {
        __syncthreads();
        for (int t = threadIdx.x; t < KNN_TILE; t += 256) {
            int j = t0 + t;
            float a = xyz[j * 3 + 0];
            float b = xyz[j * 3 + 1];
            float c = xyz[j * 3 + 2];
            buf[t] = make_float4(a, b, c, fmaf(a, a, fmaf(b, b, c * c)));
        }
        __syncthreads();

        #pragma unroll 4
        for (int jj = lane; jj < KNN_TILE; jj += 32) {
            float4 p = buf[jj];
            float dot = fmaf(xi0, p.x, fmaf(xi1, p.y, xi2 * p.z));
            float dist = (sqi + p.w) - 2.0f * dot;
            int j = t0 + jj;
            if (j == q) dist = 1e30f;
            if (dist < d16[KNN_K - 1]) {
                float dk = dist; int ik = j;
                #pragma unroll
                for (int s = 0; s < KNN_K; s++) {
                    if (dk < d16[s]) {
                        float tf = d16[s]; d16[s] = dk; dk = tf;
                        int   ti = i16[s]; i16[s] = ik; ik = ti;
                    }
                }
            }
        }
    }
    __syncthreads();

    DI* pairs = (DI*)buf;
    DI* wp = pairs + warp * (KNN_K * 32);
    #pragma unroll
    for (int s = 0; s < KNN_K; s++) {
        DI e; e.d = d16[s]; e.i = i16[s];
        wp[s * 32 + lane] = e;
    }
    __syncwarp();

    int ptr = 0;
    #pragma unroll 1
    for (int r = 0; r < KNN_K; r++) {
        DI h = wp[ptr * 32 + lane];
        float bd = h.d; int bi = h.i;
        #pragma unroll
        for (int off = 16; off > 0; off >>= 1) {
            float od = __shfl_xor_sync(0xFFFFFFFFu, bd, off);
            int   oi = __shfl_xor_sync(0xFFFFFFFFu, bi, off);
            if (od < bd || (od == bd && oi < bi)) { bd = od; bi = oi; }
        }
        if (h.d == bd && h.i == bi) ptr++;
        if (lane == 0) g_nbr[q * KNN_K + r] = bi;
    }
}

// ---------------- GEMM1 (f32x2) ----------------------------------------------
#define BM 64
#define BN 64
#define BK 16
__global__ __launch_bounds__(256)
void gemm_bias(const float* __restrict__ Xp, const float* __restrict__ Wp,
               const float* __restrict__ bias, float* __restrict__ C,
               int M, int Nc, int Kd, int bias_cols) {
    __shared__ __align__(16) float Xs[BK][BM];
    __shared__ __align__(16) float Ws[BK][BN];
    int tid = threadIdx.x;
    int tx = tid % 16, ty = tid / 16;
    int bm = blockIdx.y * BM, bn = blockIdx.x * BN;

    u64 acc[4][2];
    #pragma unroll
    for (int u = 0; u < 4; u++) { acc[u][0] = 0ull; acc[u][1] = 0ull; }

    for (int k0 = 0; k0 < Kd; k0 += BK) {
        for (int l = tid; l < BM * BK; l += 256) {
            int m = l / BK, kk = l % BK;
            float v = 0.f;
            if (k0 + kk < Kd) v = Xp[(bm + m) * Kd + k0 + kk];
            Xs[kk][m] = v;
        }
        for (int l = tid; l < BN * BK; l += 256) {
            int kk = l / BN, n = l % BN;
            float v = 0.f;
            if (k0 + kk < Kd) v = Wp[(k0 + kk) * Nc + bn + n];
            Ws[kk][n] = v;
        }
        __syncthreads();
        #pragma unroll
        for (int kk = 0; kk < BK; kk++) {
            float4 av = *(const float4*)&Xs[kk][ty * 4];
            ulonglong2 bq = *(const ulonglong2*)&Ws[kk][tx * 4];
            u64 a0 = pack2(av.x, av.x);
            u64 a1 = pack2(av.y, av.y);
            u64 a2 = pack2(av.z, av.z);
            u64 a3 = pack2(av.w, av.w);
            acc[0][0] = fma2(a0, bq.x, acc[0][0]);
            acc[0][1] = fma2(a0, bq.y, acc[0][1]);
            acc[1][0] = fma2(a1, bq.x, acc[1][0]);
            acc[1][1] = fma2(a1, bq.y, acc[1][1]);
            acc[2][0] = fma2(a2, bq.x, acc[2][0]);
            acc[2][1] = fma2(a2, bq.y, acc[2][1]);
            acc[3][0] = fma2(a3, bq.x, acc[3][0]);
            acc[3][1] = fma2(a3, bq.y, acc[3][1]);
        }
        __syncthreads();
    }
    #pragma unroll
    for (int u = 0; u < 4; u++) {
        int m = bm + ty * 4 + u;
        float2 v01 = unpack2(acc[u][0]);
        float2 v23 = unpack2(acc[u][1]);
        float vals[4] = {v01.x, v01.y, v23.x, v23.y};
        #pragma unroll
        for (int v = 0; v < 4; v++) {
            int n = bn + tx * 4 + v;
            float val = vals[v];
            if (n < bias_cols) val += bias[n];
            C[m * Nc + n] = val;
        }
    }
}

// ---------------- edge MMA kernel: warp-level HMMA fp16 ---------------------
// Per CTA: 8 points, rows = 128 edges. D[128x256] = H[128x256] @ W2t[256x256]^T
// SMEM: Hs 128x256 fp16 (64KB), Ws 256x256 fp16 (128KB), both row-stride 512B
// with 16B-granule XOR swizzle: addr = row*512 + (colbyte ^ ((row&7)<<4)).
#define HS_OFF   0
#define WS_OFF   65536
#define NBR_OFF  196608          // 128 ints
#define B2_OFF   197632          // 256 floats
#define ESMEM_SZ (198656 + 1024)

__global__ __launch_bounds__(256, 1)
void edge_mma(const float* __restrict__ AB, const __half* __restrict__ W2t,
              const float* __restrict__ b2, float* __restrict__ out, int ostride) {
    extern __shared__ __align__(16) char dsm[];
    uint32_t raw = smem_u32(dsm);
    uint32_t base = (raw + 1023u) & ~1023u;
    char* sm = dsm + (base - raw);

    int tid = threadIdx.x;
    int wid = tid >> 5, lane = tid & 31;

    int* snbr = (int*)(sm + NBR_OFF);
    float* b2s = (float*)(sm + B2_OFF);
    if (tid < 128) snbr[tid] = g_nbr[blockIdx.x * 128 + tid];
    b2s[tid] = b2[tid];

    // --- load W2t into swizzled SMEM: 8192 x 16B chunks ---
    {
        const uint4* src = (const uint4*)W2t;
        #pragma unroll
        for (int it = 0; it < 32; it++) {
            int i = it * 256 + tid;           // chunk index
            int n = i >> 5, kb = i & 31;      // row n, 16B-chunk kb
            uint32_t off = (uint32_t)(n * 512 + ((kb * 16) ^ ((n & 7) << 4)));
            *(uint4*)(sm + WS_OFF + off) = src[i];
        }
    }
    __syncthreads();   // snbr ready before H build reads it

    // --- build H tile: h = relu(A_i + B_j), fp16, swizzled ---
    {
        int halfrow = (tid >> 7) * 64;
        int c2 = (tid & 127) * 2;             // even column index
        uint32_t cb = (uint32_t)(c2 * 2);     // column byte offset
        float2 a2 = make_float2(0.f, 0.f);
        #pragma unroll 4
        for (int rr = 0; rr < 64; rr++) {
            int r = halfrow + rr;
            if ((r & 15) == 0) {
                int pt = blockIdx.x * 8 + (r >> 4);
                a2 = *(const float2*)&AB[pt * NW + c2];
            }
            int j = snbr[r];
            float2 b = *(const float2*)&AB[j * NW + DTOK + c2];
            float h0 = fmaxf(a2.x + b.x, 0.f);
            float h1 = fmaxf(a2.y + b.y, 0.f);
            uint32_t off = (uint32_t)(r * 512) + (cb ^ ((uint32_t)(r & 7) << 4));
            *(__half2*)(sm + HS_OFF + off) = __floats2half2_rn(h0, h1);
        }
    }
    __syncthreads();

    // --- per-warp MMA: point pt = wid, 16 rows x 256 cols ---
    int pt = wid;
    int ptg = blockIdx.x * 8 + pt;
    uint32_t swz = (uint32_t)(lane & 7) << 4;
    uint32_t rowA = (uint32_t)(pt * 16 + ((lane >> 3) & 1) * 8 + (lane & 7));
    uint32_t baseA = base + HS_OFF + rowA * 512;
    uint32_t cbA_add = (uint32_t)(lane >> 4) * 16;
    uint32_t nB_part = (uint32_t)((lane >> 4) * 8 + (lane & 7));
    uint32_t baseB = base + WS_OFF + nB_part * 512;
    uint32_t cbB_add = (uint32_t)((lane >> 3) & 1) * 16;

    int tg = lane & 3;            // thread-in-group: column pair selector
    #pragma unroll 1
    for (int chunk = 0; chunk < 4; chunk++) {
        int n0c = chunk * 64;
        float acc[8][4];
        #pragma unroll
        for (int t = 0; t < 8; t++)
            #pragma unroll
            for (int u = 0; u < 4; u++) acc[t][u] = 0.f;

        #pragma unroll 4
        for (int kk = 0; kk < 16; kk++) {
            uint32_t a0, a1, a2r, a3;
            uint32_t cbA = (uint32_t)(kk * 32) + cbA_add;
            ldsm_x4(a0, a1, a2r, a3, baseA + (cbA ^ swz));
            uint32_t cbB = (uint32_t)(kk * 32) + cbB_add;
            #pragma unroll
            for (int ntp = 0; ntp < 4; ntp++) {
                uint32_t b0, b1, b2r, b3;
                uint32_t nOff = (uint32_t)((n0c + ntp * 16) * 512);
                ldsm_x4(b0, b1, b2r, b3, baseB + nOff + (cbB ^ swz));
                mma_f16(acc[ntp * 2 + 0], a0, a1, a2r, a3, b0, b1);
                mma_f16(acc[ntp * 2 + 1], a0, a1, a2r, a3, b2r, b3);
            }
        }

        // epilogue: max over 16 edge rows per column
        #pragma unroll
        for (int t = 0; t < 8; t++) {
            float m0 = fmaxf(acc[t][0], acc[t][2]);
            float m1 = fmaxf(acc[t][1], acc[t][3]);
            #pragma unroll
            for (int off = 4; off <= 16; off <<= 1) {
                m0 = fmaxf(m0, __shfl_xor_sync(0xFFFFFFFFu, m0, off));
                m1 = fmaxf(m1, __shfl_xor_sync(0xFFFFFFFFu, m1, off));
            }
            if (lane < 4) {
                int col = n0c + t * 8 + tg * 2;
                // scalar stores: ostride may be odd (D_IN=259) -> no STG.64
                out[ptg * ostride + col]     = m0 + b2s[col];
                out[ptg * ostride + col + 1] = m1 + b2s[col + 1];
            }
        }
    }
}

// ---------------- launch ----------------------------------------------------
extern "C" void kernel_launch(void* const* d_in, const int* in_sizes, int n_in,
                              void* d_out, int out_size) {
    const float* xyz  = (const float*)d_in[0];
    const float* feat = (const float*)d_in[1];
    const float* W1a  = (const float*)d_in[2];
    const float* b1a  = (const float*)d_in[3];
    const float* W2a  = (const float*)d_in[4];
    const float* b2a  = (const float*)d_in[5];
    const float* W1b  = (const float*)d_in[6];
    const float* b1b  = (const float*)d_in[7];
    const float* W2b  = (const float*)d_in[8];
    const float* b2b  = (const float*)d_in[9];
    float* out = (float*)d_out;

    float *gX, *gAB, *gWa, *gWb;
    __half *gW2a, *gW2b;
    cudaGetSymbolAddress((void**)&gX,   g_X);
    cudaGetSymbolAddress((void**)&gAB,  g_AB);
    cudaGetSymbolAddress((void**)&gWa,  g_Wcat_a);
    cudaGetSymbolAddress((void**)&gWb,  g_Wcat_b);
    cudaGetSymbolAddress((void**)&gW2a, g_W2t_a);
    cudaGetSymbolAddress((void**)&gW2b, g_W2t_b);

    cudaFuncSetAttribute(edge_mma, cudaFuncAttributeMaxDynamicSharedMemorySize, ESMEM_SZ);

    // 1) weight prep
    {
        int n = D_IN * NW;
        prep_weights<<<(n + 255) / 256, 256>>>(W1a, W1b, W2a, W2b);
    }
    // 2) KNN
    knn_kernel<<<N_PTS / KNN_WPB, 256>>>(xyz);
    // 3) X1 = [feat | xyz]
    {
        int n = N_PTS * D_IN;
        build_x<<<(n + 255) / 256, 256>>>(feat, xyz);
    }
    dim3 ggrid(NW / BN, N_PTS / BM);

    // layer a
    gemm_bias<<<ggrid, 256>>>(gX, gWa, b1a, gAB, N_PTS, NW, D_IN, DTOK);
    edge_mma<<<N_PTS / 8, 256, ESMEM_SZ>>>(gAB, gW2a, b2a, gX, D_IN);

    // layer b
    gemm_bias<<<ggrid, 256>>>(gX, gWb, b1b, gAB, N_PTS, NW, D_IN, DTOK);
    edge_mma<<<N_PTS / 8, 256, ESMEM_SZ>>>(gAB, gW2b, b2b, out, DTOK);
}

// round 13
// speedup vs baseline: 3.6018x; 1.2786x over previous
#include <cuda_runtime.h>
#include <cuda_fp16.h>
#include <cstdint>

#define N_PTS 8192
#define DTOK  256
#define KNN_K 16
#define D_IN  259          // DTOK + 3
#define KPAD  272          // D_IN padded to multiple of 16 (rows 16B-aligned)
#define NW    512          // concatenated output cols of gemm1: [A | B]

typedef unsigned long long u64;

// ---------------- f32x2 packed helpers (sm_100+) ----------------------------
__device__ __forceinline__ u64 pack2(float lo, float hi) {
    u64 r;
    asm("mov.b64 %0, {%1, %2};" : "=l"(r) : "f"(lo), "f"(hi));
    return r;
}
__device__ __forceinline__ u64 fma2(u64 a, u64 b, u64 c) {
    u64 d;
    asm("fma.rn.f32x2 %0, %1, %2, %3;" : "=l"(d) : "l"(a), "l"(b), "l"(c));
    return d;
}
__device__ __forceinline__ float2 unpack2(u64 v) {
    float2 f;
    asm("mov.b64 {%0, %1}, %2;" : "=f"(f.x), "=f"(f.y) : "l"(v));
    return f;
}

// ---------------- warp MMA helpers (family-level PTX) ------------------------
__device__ __forceinline__ uint32_t smem_u32(const void* p) {
    uint32_t a;
    asm("{ .reg .u64 t; cvta.to.shared.u64 t, %1; cvt.u32.u64 %0, t; }" : "=r"(a) : "l"(p));
    return a;
}
__device__ __forceinline__ void ldsm_x4(uint32_t& r0, uint32_t& r1, uint32_t& r2,
                                        uint32_t& r3, uint32_t addr) {
    asm volatile("ldmatrix.sync.aligned.m8n8.x4.shared.b16 {%0,%1,%2,%3}, [%4];"
                 : "=r"(r0), "=r"(r1), "=r"(r2), "=r"(r3) : "r"(addr));
}
__device__ __forceinline__ void mma_f16(float* c, uint32_t a0, uint32_t a1,
                                        uint32_t a2, uint32_t a3,
                                        uint32_t b0, uint32_t b1) {
    asm volatile(
        "mma.sync.aligned.m16n8k16.row.col.f32.f16.f16.f32 "
        "{%0,%1,%2,%3}, {%4,%5,%6,%7}, {%8,%9}, {%0,%1,%2,%3};"
        : "+f"(c[0]), "+f"(c[1]), "+f"(c[2]), "+f"(c[3])
        : "r"(a0), "r"(a1), "r"(a2), "r"(a3), "r"(b0), "r"(b1));
}

// ---------------- scratch (device globals; no allocation allowed) ----------
__device__ __align__(16) float g_X[N_PTS * KPAD];     // K-padded layer input
__device__ __align__(16) float g_AB[N_PTS * NW];
__device__ __align__(16) float g_Wcat_a[KPAD * NW];
__device__ __align__(16) float g_Wcat_b[KPAD * NW];
__device__ int   g_nbr[N_PTS * KNN_K];
__device__ __align__(16) __half g_W2t_a[DTOK * DTOK];
__device__ __align__(16) __half g_W2t_b[DTOK * DTOK];

// ---------------- weight prep ----------------------------------------------
__global__ void prep_weights(const float* __restrict__ W1a,
                             const float* __restrict__ W1b,
                             const float* __restrict__ W2a,
                             const float* __restrict__ W2b) {
    int idx = blockIdx.x * blockDim.x + threadIdx.x;
    if (idx < KPAD * NW) {
        int r = idx / NW, c = idx % NW;
        float va = 0.f, vb = 0.f;
        if (r < D_IN) {
            if (c < DTOK) {
                va = W1a[r * DTOK + c] - W1a[(D_IN + r) * DTOK + c];
                vb = W1b[r * DTOK + c] - W1b[(D_IN + r) * DTOK + c];
            } else {
                int cc = c - DTOK;
                va = W1a[(D_IN + r) * DTOK + cc];
                vb = W1b[(D_IN + r) * DTOK + cc];
            }
        }
        g_Wcat_a[idx] = va;
        g_Wcat_b[idx] = vb;
    }
    if (idx < DTOK * DTOK) {
        int n = idx / DTOK, d = idx % DTOK;
        g_W2t_a[idx] = __float2half_rn(W2a[d * DTOK + n]);
        g_W2t_b[idx] = __float2half_rn(W2b[d * DTOK + n]);
    }
}

// ---------------- build X1 = [feat | xyz | 0pad] -----------------------------
__global__ void build_x(const float* __restrict__ feat,
                        const float* __restrict__ xyz) {
    int idx = blockIdx.x * blockDim.x + threadIdx.x;
    if (idx >= N_PTS * KPAD) return;
    int i = idx / KPAD, c = idx % KPAD;
    float v = 0.f;
    if (c < DTOK) v = feat[i * DTOK + c];
    else if (c < D_IN) v = xyz[i * 3 + (c - DTOK)];
    g_X[idx] = v;
}

// ---------------- KNN: one warp per query, register top-16 ------------------
#define KNN_WPB   8
#define KNN_TILE  2048
struct DI { float d; int i; };

__global__ __launch_bounds__(256)
void knn_kernel(const float* __restrict__ xyz) {
    __shared__ __align__(16) float4 buf[KNN_TILE];
    int warp = threadIdx.x >> 5, lane = threadIdx.x & 31;
    int q = blockIdx.x * KNN_WPB + warp;

    float xi0 = xyz[q * 3 + 0];
    float xi1 = xyz[q * 3 + 1];
    float xi2 = xyz[q * 3 + 2];
    float sqi = fmaf(xi0, xi0, fmaf(xi1, xi1, xi2 * xi2));

    float d16[KNN_K];
    int   i16[KNN_K];
    #pragma unroll
    for (int s = 0; s < KNN_K; s++) { d16[s] = 1e30f; i16[s] = -1; }

    for (int t0 = 0; t0 < N_PTS; t0 += KNN_TILE) {
        __syncthreads();
        for (int t = threadIdx.x; t < KNN_TILE; t += 256) {
            int j = t0 + t;
            float a = xyz[j * 3 + 0];
            float b = xyz[j * 3 + 1];
            float c = xyz[j * 3 + 2];
            buf[t] = make_float4(a, b, c, fmaf(a, a, fmaf(b, b, c * c)));
        }
        __syncthreads();

        #pragma unroll 4
        for (int jj = lane; jj < KNN_TILE; jj += 32) {
            float4 p = buf[jj];
            float dot = fmaf(xi0, p.x, fmaf(xi1, p.y, xi2 * p.z));
            float dist = (sqi + p.w) - 2.0f * dot;
            int j = t0 + jj;
            if (j == q) dist = 1e30f;
            if (dist < d16[KNN_K - 1]) {
                float dk = dist; int ik = j;
                #pragma unroll
                for (int s = 0; s < KNN_K; s++) {
                    if (dk < d16[s]) {
                        float tf = d16[s]; d16[s] = dk; dk = tf;
                        int   ti = i16[s]; i16[s] = ik; ik = ti;
                    }
                }
            }
        }
    }
    __syncthreads();

    DI* pairs = (DI*)buf;
    DI* wp = pairs + warp * (KNN_K * 32);
    #pragma unroll
    for (int s = 0; s < KNN_K; s++) {
        DI e; e.d = d16[s]; e.i = i16[s];
        wp[s * 32 + lane] = e;
    }
    __syncwarp();

    int ptr = 0;
    #pragma unroll 1
    for (int r = 0; r < KNN_K; r++) {
        DI h = wp[ptr * 32 + lane];
        float bd = h.d; int bi = h.i;
        #pragma unroll
        for (int off = 16; off > 0; off >>= 1) {
            float od = __shfl_xor_sync(0xFFFFFFFFu, bd, off);
            int   oi = __shfl_xor_sync(0xFFFFFFFFu, bi, off);
            if (od < bd || (od == bd && oi < bi)) { bd = od; bi = oi; }
        }
        if (h.d == bd && h.i == bi) ptr++;
        if (lane == 0) g_nbr[q * KNN_K + r] = bi;
    }
}

// ---------------- GEMM1: AB[8192,512] = X[8192,KPAD] @ Wcat[KPAD,512] (+bias)
// 128x128 CTA tile, 8x8 per-thread (f32x2), K padded -> no guards.
#define BM 128
#define BN 128
#define BK 16
__global__ __launch_bounds__(256)
void gemm_bias(const float* __restrict__ Xp, const float* __restrict__ Wp,
               const float* __restrict__ bias, float* __restrict__ C,
               int bias_cols) {
    __shared__ __align__(16) float Xs[BK][BM];
    __shared__ __align__(16) float Ws[BK][BN];
    int tid = threadIdx.x;
    int tx = tid % 16, ty = tid / 16;
    int bm = blockIdx.y * BM, bn = blockIdx.x * BN;

    u64 acc[8][4];
    #pragma unroll
    for (int u = 0; u < 8; u++)
        #pragma unroll
        for (int v = 0; v < 4; v++) acc[u][v] = 0ull;

    int xm = tid & 127;           // row this thread loads for Xs
    int xq = tid >> 7;            // kk block 0/1
    int wk = tid >> 5;            // kk row for Ws (0..7, +8 on second pass)
    int wn = (tid & 31) * 4;      // n quad

    #pragma unroll 1
    for (int k0 = 0; k0 < KPAD; k0 += BK) {
        #pragma unroll
        for (int i = 0; i < 2; i++) {
            int kk = xq * 8 + i * 4;
            float4 v = *(const float4*)&Xp[(bm + xm) * KPAD + k0 + kk];
            Xs[kk + 0][xm] = v.x;
            Xs[kk + 1][xm] = v.y;
            Xs[kk + 2][xm] = v.z;
            Xs[kk + 3][xm] = v.w;
        }
        #pragma unroll
        for (int i = 0; i < 2; i++) {
            int kk = wk + i * 8;
            *(float4*)&Ws[kk][wn] = *(const float4*)&Wp[(k0 + kk) * NW + bn + wn];
        }
        __syncthreads();
        #pragma unroll
        for (int kk = 0; kk < BK; kk++) {
            float4 aLo = *(const float4*)&Xs[kk][ty * 8];
            float4 aHi = *(const float4*)&Xs[kk][ty * 8 + 4];
            ulonglong2 b01 = *(const ulonglong2*)&Ws[kk][tx * 8];
            ulonglong2 b23 = *(const ulonglong2*)&Ws[kk][tx * 8 + 4];
            u64 am[8];
            am[0] = pack2(aLo.x, aLo.x); am[1] = pack2(aLo.y, aLo.y);
            am[2] = pack2(aLo.z, aLo.z); am[3] = pack2(aLo.w, aLo.w);
            am[4] = pack2(aHi.x, aHi.x); am[5] = pack2(aHi.y, aHi.y);
            am[6] = pack2(aHi.z, aHi.z); am[7] = pack2(aHi.w, aHi.w);
            #pragma unroll
            for (int u = 0; u < 8; u++) {
                acc[u][0] = fma2(am[u], b01.x, acc[u][0]);
                acc[u][1] = fma2(am[u], b01.y, acc[u][1]);
                acc[u][2] = fma2(am[u], b23.x, acc[u][2]);
                acc[u][3] = fma2(am[u], b23.y, acc[u][3]);
            }
        }
        __syncthreads();
    }

    bool has_bias = (bn < bias_cols);
    #pragma unroll
    for (int u = 0; u < 8; u++) {
        int m = bm + ty * 8 + u;
        float out8[8];
        #pragma unroll
        for (int v = 0; v < 4; v++) {
            float2 f = unpack2(acc[u][v]);
            out8[v * 2] = f.x; out8[v * 2 + 1] = f.y;
        }
        int n0 = bn + tx * 8;
        if (has_bias) {
            #pragma unroll
            for (int v = 0; v < 8; v++) out8[v] += bias[n0 + v];
        }
        *(float4*)&C[m * NW + n0]     = make_float4(out8[0], out8[1], out8[2], out8[3]);
        *(float4*)&C[m * NW + n0 + 4] = make_float4(out8[4], out8[5], out8[6], out8[7]);
    }
}

// ---------------- edge MMA kernel: warp-level HMMA fp16, 512 threads --------
// Per CTA: 8 points, 128 edge rows. D[128x256] = H[128x256] @ W2t[256x256]^T
// 16 warps: warp w -> point (w>>1), N-half (w&1)*128 (16 rows x 128 cols).
#define HS_OFF   0
#define WS_OFF   65536
#define NBR_OFF  196608          // 128 ints
#define B2_OFF   197632          // 256 floats
#define ESMEM_SZ (198656 + 1024)

__global__ __launch_bounds__(512, 1)
void edge_mma(const float* __restrict__ AB, const __half* __restrict__ W2t,
              const float* __restrict__ b2, float* __restrict__ out, int ostride) {
    extern __shared__ __align__(16) char dsm[];
    uint32_t raw = smem_u32(dsm);
    uint32_t base = (raw + 1023u) & ~1023u;
    char* sm = dsm + (base - raw);

    int tid = threadIdx.x;
    int wid = tid >> 5, lane = tid & 31;

    int* snbr = (int*)(sm + NBR_OFF);
    float* b2s = (float*)(sm + B2_OFF);
    if (tid < 128) snbr[tid] = g_nbr[blockIdx.x * 128 + tid];
    if (tid < 256) b2s[tid] = b2[tid];

    // --- load W2t into swizzled SMEM: 8192 x 16B chunks ---
    {
        const uint4* src = (const uint4*)W2t;
        #pragma unroll
        for (int it = 0; it < 16; it++) {
            int i = it * 512 + tid;
            int n = i >> 5, kb = i & 31;
            uint32_t off = (uint32_t)(n * 512 + ((kb * 16) ^ ((n & 7) << 4)));
            *(uint4*)(sm + WS_OFF + off) = src[i];
        }
    }
    __syncthreads();   // snbr ready before H build reads it

    // --- build H tile: h = relu(A_i + B_j), fp16, swizzled (512 thr) ---
    {
        int rowgrp = tid >> 7;                // 0..3 -> 32 rows each
        int c2 = (tid & 127) * 2;             // even column index
        uint32_t cb = (uint32_t)(c2 * 2);     // column byte offset
        float2 a2 = make_float2(0.f, 0.f);
        #pragma unroll 4
        for (int rr = 0; rr < 32; rr++) {
            int r = rowgrp * 32 + rr;
            if ((r & 15) == 0) {
                int pt = blockIdx.x * 8 + (r >> 4);
                a2 = *(const float2*)&AB[pt * NW + c2];
            }
            int j = snbr[r];
            float2 b = *(const float2*)&AB[j * NW + DTOK + c2];
            float h0 = fmaxf(a2.x + b.x, 0.f);
            float h1 = fmaxf(a2.y + b.y, 0.f);
            uint32_t off = (uint32_t)(r * 512) + (cb ^ ((uint32_t)(r & 7) << 4));
            *(__half2*)(sm + HS_OFF + off) = __floats2half2_rn(h0, h1);
        }
    }
    __syncthreads();

    // --- per-warp MMA: point pt = wid>>1, N-half (wid&1), 16 rows x 128 cols
    int pt = wid >> 1;
    int nhalf = wid & 1;
    int ptg = blockIdx.x * 8 + pt;
    uint32_t swz = (uint32_t)(lane & 7) << 4;
    uint32_t rowA = (uint32_t)(pt * 16 + ((lane >> 3) & 1) * 8 + (lane & 7));
    uint32_t baseA = base + HS_OFF + rowA * 512;
    uint32_t cbA_add = (uint32_t)(lane >> 4) * 16;
    uint32_t nB_part = (uint32_t)((lane >> 4) * 8 + (lane & 7));
    uint32_t baseB = base + WS_OFF + nB_part * 512;
    uint32_t cbB_add = (uint32_t)((lane >> 3) & 1) * 16;

    int tg = lane & 3;            // thread-in-group: column pair selector
    #pragma unroll 1
    for (int chunk = 0; chunk < 2; chunk++) {
        int n0c = nhalf * 128 + chunk * 64;
        float acc[8][4];
        #pragma unroll
        for (int t = 0; t < 8; t++)
            #pragma unroll
            for (int u = 0; u < 4; u++) acc[t][u] = 0.f;

        #pragma unroll 4
        for (int kk = 0; kk < 16; kk++) {
            uint32_t a0, a1, a2r, a3;
            uint32_t cbA = (uint32_t)(kk * 32) + cbA_add;
            ldsm_x4(a0, a1, a2r, a3, baseA + (cbA ^ swz));
            uint32_t cbB = (uint32_t)(kk * 32) + cbB_add;
            #pragma unroll
            for (int ntp = 0; ntp < 4; ntp++) {
                uint32_t b0, b1, b2r, b3;
                uint32_t nOff = (uint32_t)((n0c + ntp * 16) * 512);
                ldsm_x4(b0, b1, b2r, b3, baseB + nOff + (cbB ^ swz));
                mma_f16(acc[ntp * 2 + 0], a0, a1, a2r, a3, b0, b1);
                mma_f16(acc[ntp * 2 + 1], a0, a1, a2r, a3, b2r, b3);
            }
        }

        // epilogue: max over 16 edge rows per column
        #pragma unroll
        for (int t = 0; t < 8; t++) {
            float m0 = fmaxf(acc[t][0], acc[t][2]);
            float m1 = fmaxf(acc[t][1], acc[t][3]);
            #pragma unroll
            for (int off = 4; off <= 16; off <<= 1) {
                m0 = fmaxf(m0, __shfl_xor_sync(0xFFFFFFFFu, m0, off));
                m1 = fmaxf(m1, __shfl_xor_sync(0xFFFFFFFFu, m1, off));
            }
            if (lane < 4) {
                int col = n0c + t * 8 + tg * 2;
                // ostride even (272 or 256) and col even -> 8B aligned
                *(float2*)&out[ptg * ostride + col] =
                    make_float2(m0 + b2s[col], m1 + b2s[col + 1]);
            }
        }
    }
}

// ---------------- launch ----------------------------------------------------
extern "C" void kernel_launch(void* const* d_in, const int* in_sizes, int n_in,
                              void* d_out, int out_size) {
    const float* xyz  = (const float*)d_in[0];
    const float* feat = (const float*)d_in[1];
    const float* W1a  = (const float*)d_in[2];
    const float* b1a  = (const float*)d_in[3];
    const float* W2a  = (const float*)d_in[4];
    const float* b2a  = (const float*)d_in[5];
    const float* W1b  = (const float*)d_in[6];
    const float* b1b  = (const float*)d_in[7];
    const float* W2b  = (const float*)d_in[8];
    const float* b2b  = (const float*)d_in[9];
    float* out = (float*)d_out;

    float *gX, *gAB, *gWa, *gWb;
    __half *gW2a, *gW2b;
    cudaGetSymbolAddress((void**)&gX,   g_X);
    cudaGetSymbolAddress((void**)&gAB,  g_AB);
    cudaGetSymbolAddress((void**)&gWa,  g_Wcat_a);
    cudaGetSymbolAddress((void**)&gWb,  g_Wcat_b);
    cudaGetSymbolAddress((void**)&gW2a, g_W2t_a);
    cudaGetSymbolAddress((void**)&gW2b, g_W2t_b);

    cudaFuncSetAttribute(edge_mma, cudaFuncAttributeMaxDynamicSharedMemorySize, ESMEM_SZ);

    // 1) weight prep
    {
        int n = KPAD * NW;
        prep_weights<<<(n + 255) / 256, 256>>>(W1a, W1b, W2a, W2b);
    }
    // 2) KNN
    knn_kernel<<<N_PTS / KNN_WPB, 256>>>(xyz);
    // 3) X1 = [feat | xyz | 0]
    {
        int n = N_PTS * KPAD;
        build_x<<<(n + 255) / 256, 256>>>(feat, xyz);
    }
    dim3 ggrid(NW / BN, N_PTS / BM);

    // layer a
    gemm_bias<<<ggrid, 256>>>(gX, gWa, b1a, gAB, DTOK);
    edge_mma<<<N_PTS / 8, 512, ESMEM_SZ>>>(gAB, gW2a, b2a, gX, KPAD);

    // layer b
    gemm_bias<<<ggrid, 256>>>(gX, gWb, b1b, gAB, DTOK);
    edge_mma<<<N_PTS / 8, 512, ESMEM_SZ>>>(gAB, gW2b, b2b, out, DTOK);
}